// round 11
// baseline (speedup 1.0000x reference)
#include <cuda_runtime.h>
#include <cuda_bf16.h>
#include <cstdint>

#define N_NODES 100000
#define N_EDGES 1600000
#define IN_F    128
#define OUT_F   128

// ---------------- scratch (static device globals; no runtime allocation) ----
__device__ int   g_deg[N_NODES];
__device__ int   g_off[N_NODES + 1];
__device__ int   g_pos[N_NODES];
__device__ int   g_csr[N_EDGES];
__device__ int   g_bsum[128];            // 98 scan blocks used
__device__ float g_aggn[(size_t)N_NODES * IN_F];   // norm * segment_sum(feat[src], dst)

// ---------------- CSR build ------------------------------------------------
__global__ void zero_kernel() {
    int i = blockIdx.x * 256 + threadIdx.x;
    if (i < N_NODES) { g_deg[i] = 0; g_pos[i] = 0; }
}

__global__ void count_kernel(const int* __restrict__ dst) {
    int e = blockIdx.x * 256 + threadIdx.x;
    if (e < N_EDGES) atomicAdd(&g_deg[dst[e]], 1);
}

// blocks of 1024 elements, 256 threads x 4 elems/thread. Exclusive scan
// within block into g_off, block total into g_bsum.
__global__ void scanA_kernel() {
    __shared__ int sh[256];
    int t = threadIdx.x;
    int base = blockIdx.x * 1024 + t * 4;
    int v[4];
#pragma unroll
    for (int j = 0; j < 4; j++)
        v[j] = (base + j < N_NODES) ? g_deg[base + j] : 0;
    int tsum = v[0] + v[1] + v[2] + v[3];
    sh[t] = tsum;
    __syncthreads();
#pragma unroll
    for (int off = 1; off < 256; off <<= 1) {
        int x = (t >= off) ? sh[t - off] : 0;
        __syncthreads();
        sh[t] += x;
        __syncthreads();
    }
    int run = sh[t] - tsum;                 // exclusive prefix of this thread
    if (t == 255) g_bsum[blockIdx.x] = sh[255];
#pragma unroll
    for (int j = 0; j < 4; j++) {
        if (base + j < N_NODES) g_off[base + j] = run;
        run += v[j];
    }
}

__global__ void scanB_kernel() {            // 1 block, 128 threads, 98 sums
    __shared__ int sh[128];
    int t = threadIdx.x;
    int v = (t < 98) ? g_bsum[t] : 0;
    sh[t] = v;
    __syncthreads();
#pragma unroll
    for (int off = 1; off < 128; off <<= 1) {
        int x = (t >= off) ? sh[t - off] : 0;
        __syncthreads();
        sh[t] += x;
        __syncthreads();
    }
    if (t < 98) g_bsum[t] = sh[t] - v;      // exclusive
}

__global__ void scanC_kernel() {
    int i = blockIdx.x * 256 + threadIdx.x;
    if (i < N_NODES) g_off[i] += g_bsum[i >> 10];
    if (i == 0) g_off[N_NODES] = N_EDGES;
}

__global__ void scatter_kernel(const int* __restrict__ src,
                               const int* __restrict__ dst) {
    int e = blockIdx.x * 256 + threadIdx.x;
    if (e < N_EDGES) {
        int d = dst[e];
        int p = g_off[d] + atomicAdd(&g_pos[d], 1);
        g_csr[p] = src[e];
    }
}

// ---------------- aggregation: one warp per node ---------------------------
__global__ void agg_kernel(const float4* __restrict__ feat4) {
    int warp = (blockIdx.x * blockDim.x + threadIdx.x) >> 5;
    int lane = threadIdx.x & 31;
    if (warp >= N_NODES) return;
    int s = g_off[warp];
    int e = g_off[warp + 1];

    float4 a0 = make_float4(0.f, 0.f, 0.f, 0.f);
    float4 a1 = make_float4(0.f, 0.f, 0.f, 0.f);
    float4 a2 = make_float4(0.f, 0.f, 0.f, 0.f);
    float4 a3 = make_float4(0.f, 0.f, 0.f, 0.f);

    int j = s;
    for (; j + 4 <= e; j += 4) {
        int s0 = g_csr[j], s1 = g_csr[j + 1], s2 = g_csr[j + 2], s3 = g_csr[j + 3];
        float4 v0 = feat4[s0 * 32 + lane];
        float4 v1 = feat4[s1 * 32 + lane];
        float4 v2 = feat4[s2 * 32 + lane];
        float4 v3 = feat4[s3 * 32 + lane];
        a0.x += v0.x; a0.y += v0.y; a0.z += v0.z; a0.w += v0.w;
        a1.x += v1.x; a1.y += v1.y; a1.z += v1.z; a1.w += v1.w;
        a2.x += v2.x; a2.y += v2.y; a2.z += v2.z; a2.w += v2.w;
        a3.x += v3.x; a3.y += v3.y; a3.z += v3.z; a3.w += v3.w;
    }
    for (; j < e; j++) {
        float4 v = feat4[g_csr[j] * 32 + lane];
        a0.x += v.x; a0.y += v.y; a0.z += v.z; a0.w += v.w;
    }
    a0.x += a1.x + a2.x + a3.x;
    a0.y += a1.y + a2.y + a3.y;
    a0.z += a1.z + a2.z + a3.z;
    a0.w += a1.w + a2.w + a3.w;

    int deg = e - s;
    float norm = (deg > 0) ? (1.0f / (float)deg) : 1.0f;
    a0.x *= norm; a0.y *= norm; a0.z *= norm; a0.w *= norm;

    ((float4*)g_aggn)[warp * 32 + lane] = a0;
}

// ---------------- fused GEMM: out = relu([feat|aggn] @ [Wv;Wu] + bias) ------
// M=100000, K=256, N=128. Block tile 128x128, BK=32, 256 threads, 8x8 micro.
#define BM 128
#define BN 128
#define BK 32

__global__ void __launch_bounds__(256, 2)
gemm_kernel(const float* __restrict__ feat,
            const float* __restrict__ Wv,
            const float* __restrict__ Wu,
            const float* __restrict__ bias,
            float* __restrict__ out) {
    __shared__ float As[BM][BK + 1];
    __shared__ float Bs[BK][BN];

    int t  = threadIdx.x;
    int tx = t & 15;
    int ty = t >> 4;
    int R  = blockIdx.x * BM;

    float acc[8][8];
#pragma unroll
    for (int i = 0; i < 8; i++)
#pragma unroll
        for (int j = 0; j < 8; j++) acc[i][j] = 0.f;

    for (int kc = 0; kc < 8; kc++) {
        int k0 = kc * BK;
        const float* Asrc = (k0 < 128) ? feat : (const float*)g_aggn;
        const float* Bsrc = (k0 < 128) ? Wv : Wu;
        int ka = k0 & 127;

        // load A tile (128 x 32), 4 passes of 256 threads, float4 each
#pragma unroll
        for (int p = 0; p < 4; p++) {
            int L   = p * 256 + t;
            int row = L >> 3;
            int kq  = (L & 7) * 4;
            float4 v = make_float4(0.f, 0.f, 0.f, 0.f);
            int gr = R + row;
            if (gr < N_NODES)
                v = *(const float4*)(Asrc + (size_t)gr * 128 + ka + kq);
            As[row][kq + 0] = v.x;
            As[row][kq + 1] = v.y;
            As[row][kq + 2] = v.z;
            As[row][kq + 3] = v.w;
        }
        // load B tile (32 x 128)
#pragma unroll
        for (int p = 0; p < 4; p++) {
            int L  = p * 256 + t;
            int kr = L >> 5;
            int nq = (L & 31) * 4;
            float4 v = *(const float4*)(Bsrc + (size_t)(ka + kr) * 128 + nq);
            *(float4*)&Bs[kr][nq] = v;
        }
        __syncthreads();

#pragma unroll 4
        for (int kk = 0; kk < BK; kk++) {
            float a[8], b[8];
#pragma unroll
            for (int i = 0; i < 8; i++) a[i] = As[ty * 8 + i][kk];
#pragma unroll
            for (int j = 0; j < 8; j++) b[j] = Bs[kk][tx * 8 + j];
#pragma unroll
            for (int i = 0; i < 8; i++)
#pragma unroll
                for (int j = 0; j < 8; j++)
                    acc[i][j] = fmaf(a[i], b[j], acc[i][j]);
        }
        __syncthreads();
    }

    // epilogue: + bias, relu, store
    float bs[8];
#pragma unroll
    for (int j = 0; j < 8; j++) bs[j] = bias[tx * 8 + j];

#pragma unroll
    for (int i = 0; i < 8; i++) {
        int gr = R + ty * 8 + i;
        if (gr < N_NODES) {
            float4 o0, o1;
            o0.x = fmaxf(acc[i][0] + bs[0], 0.f);
            o0.y = fmaxf(acc[i][1] + bs[1], 0.f);
            o0.z = fmaxf(acc[i][2] + bs[2], 0.f);
            o0.w = fmaxf(acc[i][3] + bs[3], 0.f);
            o1.x = fmaxf(acc[i][4] + bs[4], 0.f);
            o1.y = fmaxf(acc[i][5] + bs[5], 0.f);
            o1.z = fmaxf(acc[i][6] + bs[6], 0.f);
            o1.w = fmaxf(acc[i][7] + bs[7], 0.f);
            float* op = out + (size_t)gr * 128 + tx * 8;
            *(float4*)(op)     = o0;
            *(float4*)(op + 4) = o1;
        }
    }
}

// ---------------- launch ----------------------------------------------------
extern "C" void kernel_launch(void* const* d_in, const int* in_sizes, int n_in,
                              void* d_out, int out_size) {
    const float* feat = (const float*)d_in[0];
    const float* wu   = (const float*)d_in[1];
    const float* wv   = (const float*)d_in[2];
    const float* bias = (const float*)d_in[3];
    const int*   src  = (const int*)d_in[4];
    const int*   dst  = (const int*)d_in[5];
    float*       out  = (float*)d_out;

    (void)in_sizes; (void)n_in; (void)out_size;

    zero_kernel   <<<391, 256>>>();
    count_kernel  <<<(N_EDGES + 255) / 256, 256>>>(dst);
    scanA_kernel  <<<98, 256>>>();
    scanB_kernel  <<<1, 128>>>();
    scanC_kernel  <<<391, 256>>>();
    scatter_kernel<<<(N_EDGES + 255) / 256, 256>>>(src, dst);
    agg_kernel    <<<(N_NODES + 7) / 8, 256>>>((const float4*)feat);
    gemm_kernel   <<<(N_NODES + BM - 1) / BM, 256>>>(feat, wv, wu, bias, out);
}

// round 12
// speedup vs baseline: 1.0373x; 1.0373x over previous
#include <cuda_runtime.h>
#include <cuda_bf16.h>
#include <cstdint>

#define N_NODES 100000
#define N_EDGES 1600000
#define IN_F    128
#define OUT_F   128

// ---------------- scratch (static device globals; no runtime allocation) ----
__device__ int   g_deg[N_NODES];
__device__ int   g_off[N_NODES + 1];
__device__ int   g_pos[N_NODES];
__device__ int   g_csr[N_EDGES];
__device__ int   g_bsum[128];            // 98 scan blocks used
__device__ float g_aggn[(size_t)N_NODES * IN_F];   // norm * segment_sum(feat[src], dst)

// ---------------- packed f32x2 helpers (sm_103a FFMA2) ----------------------
__device__ __forceinline__ unsigned long long fma_f32x2(unsigned long long a,
                                                        unsigned long long b,
                                                        unsigned long long c) {
    unsigned long long d;
    asm("fma.rn.f32x2 %0, %1, %2, %3;" : "=l"(d) : "l"(a), "l"(b), "l"(c));
    return d;
}
__device__ __forceinline__ unsigned long long pack_dup(float x) {
    unsigned long long d;
    asm("mov.b64 %0, {%1, %1};" : "=l"(d) : "f"(x));
    return d;
}
__device__ __forceinline__ float2 unpack_f32x2(unsigned long long v) {
    float lo, hi;
    asm("mov.b64 {%0, %1}, %2;" : "=f"(lo), "=f"(hi) : "l"(v));
    return make_float2(lo, hi);
}

// ---------------- CSR build ------------------------------------------------
__global__ void zero_kernel() {
    int i = blockIdx.x * 256 + threadIdx.x;
    if (i < N_NODES) { g_deg[i] = 0; g_pos[i] = 0; }
}

__global__ void count_kernel(const int* __restrict__ dst) {
    int e = blockIdx.x * 256 + threadIdx.x;
    if (e < N_EDGES) atomicAdd(&g_deg[dst[e]], 1);
}

// blocks of 1024 elements, 256 threads x 4 elems/thread. Exclusive scan
// within block into g_off, block total into g_bsum.
__global__ void scanA_kernel() {
    __shared__ int sh[256];
    int t = threadIdx.x;
    int base = blockIdx.x * 1024 + t * 4;
    int v[4];
#pragma unroll
    for (int j = 0; j < 4; j++)
        v[j] = (base + j < N_NODES) ? g_deg[base + j] : 0;
    int tsum = v[0] + v[1] + v[2] + v[3];
    sh[t] = tsum;
    __syncthreads();
#pragma unroll
    for (int off = 1; off < 256; off <<= 1) {
        int x = (t >= off) ? sh[t - off] : 0;
        __syncthreads();
        sh[t] += x;
        __syncthreads();
    }
    int run = sh[t] - tsum;                 // exclusive prefix of this thread
    if (t == 255) g_bsum[blockIdx.x] = sh[255];
#pragma unroll
    for (int j = 0; j < 4; j++) {
        if (base + j < N_NODES) g_off[base + j] = run;
        run += v[j];
    }
}

__global__ void scanB_kernel() {            // 1 block, 128 threads, 98 sums
    __shared__ int sh[128];
    int t = threadIdx.x;
    int v = (t < 98) ? g_bsum[t] : 0;
    sh[t] = v;
    __syncthreads();
#pragma unroll
    for (int off = 1; off < 128; off <<= 1) {
        int x = (t >= off) ? sh[t - off] : 0;
        __syncthreads();
        sh[t] += x;
        __syncthreads();
    }
    if (t < 98) g_bsum[t] = sh[t] - v;      // exclusive
}

__global__ void scanC_kernel() {
    int i = blockIdx.x * 256 + threadIdx.x;
    if (i < N_NODES) g_off[i] += g_bsum[i >> 10];
    if (i == 0) g_off[N_NODES] = N_EDGES;
}

__global__ void scatter_kernel(const int* __restrict__ src,
                               const int* __restrict__ dst) {
    int e = blockIdx.x * 256 + threadIdx.x;
    if (e < N_EDGES) {
        int d = dst[e];
        int p = g_off[d] + atomicAdd(&g_pos[d], 1);
        g_csr[p] = src[e];
    }
}

// ---------------- aggregation: one warp per node ---------------------------
__global__ void agg_kernel(const float4* __restrict__ feat4) {
    int warp = (blockIdx.x * blockDim.x + threadIdx.x) >> 5;
    int lane = threadIdx.x & 31;
    if (warp >= N_NODES) return;
    int s = g_off[warp];
    int e = g_off[warp + 1];

    float4 a0 = make_float4(0.f, 0.f, 0.f, 0.f);
    float4 a1 = make_float4(0.f, 0.f, 0.f, 0.f);
    float4 a2 = make_float4(0.f, 0.f, 0.f, 0.f);
    float4 a3 = make_float4(0.f, 0.f, 0.f, 0.f);

    int j = s;
    for (; j + 4 <= e; j += 4) {
        int s0 = g_csr[j], s1 = g_csr[j + 1], s2 = g_csr[j + 2], s3 = g_csr[j + 3];
        float4 v0 = feat4[s0 * 32 + lane];
        float4 v1 = feat4[s1 * 32 + lane];
        float4 v2 = feat4[s2 * 32 + lane];
        float4 v3 = feat4[s3 * 32 + lane];
        a0.x += v0.x; a0.y += v0.y; a0.z += v0.z; a0.w += v0.w;
        a1.x += v1.x; a1.y += v1.y; a1.z += v1.z; a1.w += v1.w;
        a2.x += v2.x; a2.y += v2.y; a2.z += v2.z; a2.w += v2.w;
        a3.x += v3.x; a3.y += v3.y; a3.z += v3.z; a3.w += v3.w;
    }
    for (; j < e; j++) {
        float4 v = feat4[g_csr[j] * 32 + lane];
        a0.x += v.x; a0.y += v.y; a0.z += v.z; a0.w += v.w;
    }
    a0.x += a1.x + a2.x + a3.x;
    a0.y += a1.y + a2.y + a3.y;
    a0.z += a1.z + a2.z + a3.z;
    a0.w += a1.w + a2.w + a3.w;

    int deg = e - s;
    float norm = (deg > 0) ? (1.0f / (float)deg) : 1.0f;
    a0.x *= norm; a0.y *= norm; a0.z *= norm; a0.w *= norm;

    ((float4*)g_aggn)[warp * 32 + lane] = a0;
}

// ---------------- fused GEMM: out = relu([feat|aggn] @ [Wv;Wu] + bias) ------
// M=100000, K=256, N=128. Block tile 128x128, BK=32, 256 threads, 8x8 micro.
// Inner loop uses packed fma.rn.f32x2 (FFMA2): 2 exact fp32 MACs per issue.
#define BM 128
#define BN 128
#define BK 32

__global__ void __launch_bounds__(256, 2)
gemm_kernel(const float* __restrict__ feat,
            const float* __restrict__ Wv,
            const float* __restrict__ Wu,
            const float* __restrict__ bias,
            float* __restrict__ out) {
    __shared__ float As[BM][BK + 1];
    __shared__ float Bs[BK][BN];

    int t  = threadIdx.x;
    int tx = t & 15;
    int ty = t >> 4;
    int R  = blockIdx.x * BM;

    // acc2[i][jp] holds output cols (tx*8 + 2*jp, tx*8 + 2*jp + 1) for row ty*8+i
    unsigned long long acc2[8][4];
#pragma unroll
    for (int i = 0; i < 8; i++)
#pragma unroll
        for (int jp = 0; jp < 4; jp++) acc2[i][jp] = 0ULL;

    for (int kc = 0; kc < 8; kc++) {
        int k0 = kc * BK;
        const float* Asrc = (k0 < 128) ? feat : (const float*)g_aggn;
        const float* Bsrc = (k0 < 128) ? Wv : Wu;
        int ka = k0 & 127;

        // load A tile (128 x 32), 4 passes of 256 threads, float4 each
#pragma unroll
        for (int p = 0; p < 4; p++) {
            int L   = p * 256 + t;
            int row = L >> 3;
            int kq  = (L & 7) * 4;
            float4 v = make_float4(0.f, 0.f, 0.f, 0.f);
            int gr = R + row;
            if (gr < N_NODES)
                v = *(const float4*)(Asrc + (size_t)gr * 128 + ka + kq);
            As[row][kq + 0] = v.x;
            As[row][kq + 1] = v.y;
            As[row][kq + 2] = v.z;
            As[row][kq + 3] = v.w;
        }
        // load B tile (32 x 128)
#pragma unroll
        for (int p = 0; p < 4; p++) {
            int L  = p * 256 + t;
            int kr = L >> 5;
            int nq = (L & 31) * 4;
            float4 v = *(const float4*)(Bsrc + (size_t)(ka + kr) * 128 + nq);
            *(float4*)&Bs[kr][nq] = v;
        }
        __syncthreads();

#pragma unroll 8
        for (int kk = 0; kk < BK; kk++) {
            // b: 8 floats = 4 packed f32x2, via two 16B shared loads
            ulonglong2 q0 = *(const ulonglong2*)&Bs[kk][tx * 8];
            ulonglong2 q1 = *(const ulonglong2*)&Bs[kk][tx * 8 + 4];
            // a: duplicate each scalar into both packed lanes
            unsigned long long ad[8];
#pragma unroll
            for (int i = 0; i < 8; i++) ad[i] = pack_dup(As[ty * 8 + i][kk]);
#pragma unroll
            for (int i = 0; i < 8; i++) {
                acc2[i][0] = fma_f32x2(ad[i], q0.x, acc2[i][0]);
                acc2[i][1] = fma_f32x2(ad[i], q0.y, acc2[i][1]);
                acc2[i][2] = fma_f32x2(ad[i], q1.x, acc2[i][2]);
                acc2[i][3] = fma_f32x2(ad[i], q1.y, acc2[i][3]);
            }
        }
        __syncthreads();
    }

    // epilogue: + bias, relu, store
    float bs[8];
#pragma unroll
    for (int j = 0; j < 8; j++) bs[j] = bias[tx * 8 + j];

#pragma unroll
    for (int i = 0; i < 8; i++) {
        int gr = R + ty * 8 + i;
        if (gr < N_NODES) {
            float2 c0 = unpack_f32x2(acc2[i][0]);
            float2 c1 = unpack_f32x2(acc2[i][1]);
            float2 c2 = unpack_f32x2(acc2[i][2]);
            float2 c3 = unpack_f32x2(acc2[i][3]);
            float4 o0, o1;
            o0.x = fmaxf(c0.x + bs[0], 0.f);
            o0.y = fmaxf(c0.y + bs[1], 0.f);
            o0.z = fmaxf(c1.x + bs[2], 0.f);
            o0.w = fmaxf(c1.y + bs[3], 0.f);
            o1.x = fmaxf(c2.x + bs[4], 0.f);
            o1.y = fmaxf(c2.y + bs[5], 0.f);
            o1.z = fmaxf(c3.x + bs[6], 0.f);
            o1.w = fmaxf(c3.y + bs[7], 0.f);
            float* op = out + (size_t)gr * 128 + tx * 8;
            *(float4*)(op)     = o0;
            *(float4*)(op + 4) = o1;
        }
    }
}

// ---------------- launch ----------------------------------------------------
extern "C" void kernel_launch(void* const* d_in, const int* in_sizes, int n_in,
                              void* d_out, int out_size) {
    const float* feat = (const float*)d_in[0];
    const float* wu   = (const float*)d_in[1];
    const float* wv   = (const float*)d_in[2];
    const float* bias = (const float*)d_in[3];
    const int*   src  = (const int*)d_in[4];
    const int*   dst  = (const int*)d_in[5];
    float*       out  = (float*)d_out;

    (void)in_sizes; (void)n_in; (void)out_size;

    zero_kernel   <<<391, 256>>>();
    count_kernel  <<<(N_EDGES + 255) / 256, 256>>>(dst);
    scanA_kernel  <<<98, 256>>>();
    scanB_kernel  <<<1, 128>>>();
    scanC_kernel  <<<391, 256>>>();
    scatter_kernel<<<(N_EDGES + 255) / 256, 256>>>(src, dst);
    agg_kernel    <<<(N_NODES + 7) / 8, 256>>>((const float4*)feat);
    gemm_kernel   <<<(N_NODES + BM - 1) / BM, 256>>>(feat, wv, wu, bias, out);
}

// round 13
// speedup vs baseline: 1.1746x; 1.1324x over previous
#include <cuda_runtime.h>
#include <cuda_bf16.h>
#include <cstdint>

#define N_NODES 100000
#define N_EDGES 1600000
#define IN_F    128
#define OUT_F   128

// ---------------- scratch (static device globals; no runtime allocation) ----
__device__ int   g_deg[N_NODES];
__device__ int   g_off[N_NODES + 1];
__device__ int   g_pos[N_NODES];
__device__ int   g_csr[N_EDGES];
__device__ int   g_bsum[128];            // 98 scan blocks used
__device__ float g_aggn[(size_t)N_NODES * IN_F];   // norm * segment_sum(feat[src], dst)

// ---------------- packed f32x2 helpers (sm_103a FFMA2) ----------------------
__device__ __forceinline__ unsigned long long fma_f32x2(unsigned long long a,
                                                        unsigned long long b,
                                                        unsigned long long c) {
    unsigned long long d;
    asm("fma.rn.f32x2 %0, %1, %2, %3;" : "=l"(d) : "l"(a), "l"(b), "l"(c));
    return d;
}
__device__ __forceinline__ unsigned long long pack_dup(float x) {
    unsigned long long d;
    asm("mov.b64 %0, {%1, %1};" : "=l"(d) : "f"(x));
    return d;
}
__device__ __forceinline__ float2 unpack_f32x2(unsigned long long v) {
    float lo, hi;
    asm("mov.b64 {%0, %1}, %2;" : "=f"(lo), "=f"(hi) : "l"(v));
    return make_float2(lo, hi);
}

// ---------------- CSR build ------------------------------------------------
__global__ void zero_kernel() {
    int i = blockIdx.x * 256 + threadIdx.x;
    if (i < N_NODES) { g_deg[i] = 0; g_pos[i] = 0; }
}

__global__ void count_kernel(const int* __restrict__ dst) {
    int e = blockIdx.x * 256 + threadIdx.x;
    if (e < N_EDGES) atomicAdd(&g_deg[dst[e]], 1);
}

__global__ void scanA_kernel() {
    __shared__ int sh[256];
    int t = threadIdx.x;
    int base = blockIdx.x * 1024 + t * 4;
    int v[4];
#pragma unroll
    for (int j = 0; j < 4; j++)
        v[j] = (base + j < N_NODES) ? g_deg[base + j] : 0;
    int tsum = v[0] + v[1] + v[2] + v[3];
    sh[t] = tsum;
    __syncthreads();
#pragma unroll
    for (int off = 1; off < 256; off <<= 1) {
        int x = (t >= off) ? sh[t - off] : 0;
        __syncthreads();
        sh[t] += x;
        __syncthreads();
    }
    int run = sh[t] - tsum;
    if (t == 255) g_bsum[blockIdx.x] = sh[255];
#pragma unroll
    for (int j = 0; j < 4; j++) {
        if (base + j < N_NODES) g_off[base + j] = run;
        run += v[j];
    }
}

__global__ void scanB_kernel() {
    __shared__ int sh[128];
    int t = threadIdx.x;
    int v = (t < 98) ? g_bsum[t] : 0;
    sh[t] = v;
    __syncthreads();
#pragma unroll
    for (int off = 1; off < 128; off <<= 1) {
        int x = (t >= off) ? sh[t - off] : 0;
        __syncthreads();
        sh[t] += x;
        __syncthreads();
    }
    if (t < 98) g_bsum[t] = sh[t] - v;
}

__global__ void scanC_kernel() {
    int i = blockIdx.x * 256 + threadIdx.x;
    if (i < N_NODES) g_off[i] += g_bsum[i >> 10];
    if (i == 0) g_off[N_NODES] = N_EDGES;
}

__global__ void scatter_kernel(const int* __restrict__ src,
                               const int* __restrict__ dst) {
    int e = blockIdx.x * 256 + threadIdx.x;
    if (e < N_EDGES) {
        int d = dst[e];
        int p = g_off[d] + atomicAdd(&g_pos[d], 1);
        g_csr[p] = src[e];
    }
}

// ---------------- aggregation: one warp per node ---------------------------
__global__ void agg_kernel(const float4* __restrict__ feat4) {
    int warp = (blockIdx.x * blockDim.x + threadIdx.x) >> 5;
    int lane = threadIdx.x & 31;
    if (warp >= N_NODES) return;
    int s = g_off[warp];
    int e = g_off[warp + 1];

    float4 a0 = make_float4(0.f, 0.f, 0.f, 0.f);
    float4 a1 = make_float4(0.f, 0.f, 0.f, 0.f);
    float4 a2 = make_float4(0.f, 0.f, 0.f, 0.f);
    float4 a3 = make_float4(0.f, 0.f, 0.f, 0.f);

    int j = s;
    for (; j + 4 <= e; j += 4) {
        int s0 = g_csr[j], s1 = g_csr[j + 1], s2 = g_csr[j + 2], s3 = g_csr[j + 3];
        float4 v0 = feat4[s0 * 32 + lane];
        float4 v1 = feat4[s1 * 32 + lane];
        float4 v2 = feat4[s2 * 32 + lane];
        float4 v3 = feat4[s3 * 32 + lane];
        a0.x += v0.x; a0.y += v0.y; a0.z += v0.z; a0.w += v0.w;
        a1.x += v1.x; a1.y += v1.y; a1.z += v1.z; a1.w += v1.w;
        a2.x += v2.x; a2.y += v2.y; a2.z += v2.z; a2.w += v2.w;
        a3.x += v3.x; a3.y += v3.y; a3.z += v3.z; a3.w += v3.w;
    }
    for (; j < e; j++) {
        float4 v = feat4[g_csr[j] * 32 + lane];
        a0.x += v.x; a0.y += v.y; a0.z += v.z; a0.w += v.w;
    }
    a0.x += a1.x + a2.x + a3.x;
    a0.y += a1.y + a2.y + a3.y;
    a0.z += a1.z + a2.z + a3.z;
    a0.w += a1.w + a2.w + a3.w;

    int deg = e - s;
    float norm = (deg > 0) ? (1.0f / (float)deg) : 1.0f;
    a0.x *= norm; a0.y *= norm; a0.z *= norm; a0.w *= norm;

    ((float4*)g_aggn)[warp * 32 + lane] = a0;
}

// ---------------- fused GEMM: out = relu([feat|aggn] @ [Wv;Wu] + bias) ------
// M=100000, K=256, N=128. Block tile 128x128, BK=32, 256 threads.
// As stored k-major [BK][BM+4]: a-fragment = packed f32x2 ROW-PAIRS loaded
// directly (no dup MOVs), b-fragment = two conflict-free LDS.128, b scalars
// duplicated. Micro-tile: 8 rows (4 pairs) x 8 cols {tx*4..+3, 64+tx*4..+3}.
#define BM 128
#define BN 128
#define BK 32
#define AS_LD (BM + 4)   // 132 floats per k-row: 528B, 16B-aligned, conflict-free STS

__global__ void __launch_bounds__(256, 2)
gemm_kernel(const float* __restrict__ feat,
            const float* __restrict__ Wv,
            const float* __restrict__ Wu,
            const float* __restrict__ bias,
            float* __restrict__ out) {
    __shared__ float As[BK][AS_LD];
    __shared__ float Bs[BK][BN];

    int t  = threadIdx.x;
    int tx = t & 15;
    int ty = t >> 4;
    int R  = blockIdx.x * BM;

    // acc2[p][j]: row-pair p -> rows (ty*8+2p, ty*8+2p+1); col j -> tx*4+j (j<4)
    // or 64+tx*4+(j-4). Lane lo = even row, hi = odd row.
    unsigned long long acc2[4][8];
#pragma unroll
    for (int p = 0; p < 4; p++)
#pragma unroll
        for (int j = 0; j < 8; j++) acc2[p][j] = 0ULL;

    for (int kc = 0; kc < 8; kc++) {
        int k0 = kc * BK;
        const float* Asrc = (k0 < 128) ? feat : (const float*)g_aggn;
        const float* Bsrc = (k0 < 128) ? Wv : Wu;
        int ka = k0 & 127;

        // load A tile (128 rows x 32 k) -> transpose into k-major As
#pragma unroll
        for (int pp = 0; pp < 4; pp++) {
            int L   = pp * 256 + t;
            int m   = L >> 3;
            int k4  = (L & 7) * 4;
            float4 v = make_float4(0.f, 0.f, 0.f, 0.f);
            int gr = R + m;
            if (gr < N_NODES)
                v = *(const float4*)(Asrc + (size_t)gr * 128 + ka + k4);
            As[k4 + 0][m] = v.x;
            As[k4 + 1][m] = v.y;
            As[k4 + 2][m] = v.z;
            As[k4 + 3][m] = v.w;
        }
        // load B tile (32 x 128), row-major
#pragma unroll
        for (int pp = 0; pp < 4; pp++) {
            int L  = pp * 256 + t;
            int kr = L >> 5;
            int nq = (L & 31) * 4;
            float4 v = *(const float4*)(Bsrc + (size_t)(ka + kr) * 128 + nq);
            *(float4*)&Bs[kr][nq] = v;
        }
        __syncthreads();

#pragma unroll 8
        for (int kk = 0; kk < BK; kk++) {
            // a: 8 consecutive rows = 4 packed row-pairs, 2 broadcast LDS.128
            ulonglong2 ap0 = *(const ulonglong2*)&As[kk][ty * 8];
            ulonglong2 ap1 = *(const ulonglong2*)&As[kk][ty * 8 + 4];
            // b: 8 cols via 2 conflict-free LDS.128, then dup each scalar
            float4 b0 = *(const float4*)&Bs[kk][tx * 4];
            float4 b1 = *(const float4*)&Bs[kk][64 + tx * 4];
            unsigned long long bd[8];
            bd[0] = pack_dup(b0.x); bd[1] = pack_dup(b0.y);
            bd[2] = pack_dup(b0.z); bd[3] = pack_dup(b0.w);
            bd[4] = pack_dup(b1.x); bd[5] = pack_dup(b1.y);
            bd[6] = pack_dup(b1.z); bd[7] = pack_dup(b1.w);

            unsigned long long ap[4] = {ap0.x, ap0.y, ap1.x, ap1.y};
#pragma unroll
            for (int p = 0; p < 4; p++)
#pragma unroll
                for (int j = 0; j < 8; j++)
                    acc2[p][j] = fma_f32x2(ap[p], bd[j], acc2[p][j]);
        }
        __syncthreads();
    }

    // epilogue: + bias, relu, store
    float bs[8];
#pragma unroll
    for (int j = 0; j < 4; j++) bs[j] = bias[tx * 4 + j];
#pragma unroll
    for (int j = 0; j < 4; j++) bs[4 + j] = bias[64 + tx * 4 + j];

#pragma unroll
    for (int p = 0; p < 4; p++) {
        float2 c[8];
#pragma unroll
        for (int j = 0; j < 8; j++) c[j] = unpack_f32x2(acc2[p][j]);

#pragma unroll
        for (int half = 0; half < 2; half++) {   // half 0 = even row, 1 = odd row
            int gr = R + ty * 8 + 2 * p + half;
            if (gr < N_NODES) {
                float4 o0, o1;
                float v0 = half ? c[0].y : c[0].x;
                float v1 = half ? c[1].y : c[1].x;
                float v2 = half ? c[2].y : c[2].x;
                float v3 = half ? c[3].y : c[3].x;
                float v4 = half ? c[4].y : c[4].x;
                float v5 = half ? c[5].y : c[5].x;
                float v6 = half ? c[6].y : c[6].x;
                float v7 = half ? c[7].y : c[7].x;
                o0.x = fmaxf(v0 + bs[0], 0.f);
                o0.y = fmaxf(v1 + bs[1], 0.f);
                o0.z = fmaxf(v2 + bs[2], 0.f);
                o0.w = fmaxf(v3 + bs[3], 0.f);
                o1.x = fmaxf(v4 + bs[4], 0.f);
                o1.y = fmaxf(v5 + bs[5], 0.f);
                o1.z = fmaxf(v6 + bs[6], 0.f);
                o1.w = fmaxf(v7 + bs[7], 0.f);
                float* op = out + (size_t)gr * 128;
                *(float4*)(op + tx * 4)      = o0;
                *(float4*)(op + 64 + tx * 4) = o1;
            }
        }
    }
}

// ---------------- launch ----------------------------------------------------
extern "C" void kernel_launch(void* const* d_in, const int* in_sizes, int n_in,
                              void* d_out, int out_size) {
    const float* feat = (const float*)d_in[0];
    const float* wu   = (const float*)d_in[1];
    const float* wv   = (const float*)d_in[2];
    const float* bias = (const float*)d_in[3];
    const int*   src  = (const int*)d_in[4];
    const int*   dst  = (const int*)d_in[5];
    float*       out  = (float*)d_out;

    (void)in_sizes; (void)n_in; (void)out_size;

    zero_kernel   <<<391, 256>>>();
    count_kernel  <<<(N_EDGES + 255) / 256, 256>>>(dst);
    scanA_kernel  <<<98, 256>>>();
    scanB_kernel  <<<1, 128>>>();
    scanC_kernel  <<<391, 256>>>();
    scatter_kernel<<<(N_EDGES + 255) / 256, 256>>>(src, dst);
    agg_kernel    <<<(N_NODES + 7) / 8, 256>>>((const float4*)feat);
    gemm_kernel   <<<(N_NODES + BM - 1) / BM, 256>>>(feat, wv, wu, bias, out);
}